// round 9
// baseline (speedup 1.0000x reference)
#include <cuda_runtime.h>
#include <cuda_bf16.h>

// Problem constants
#define BB   4
#define NN   256
#define CHN  128
#define CIN  1024
#define HH   120
#define WW   160
#define HWSZ (HH * WW)          // 19200
#define SRC  256

// ---------------------------------------------------------------------------
// Scratch (single __device__ global, no allocations anywhere)
// ---------------------------------------------------------------------------
// layout (floats):
//   hmid    :  B*CH*N              = 131072
//   relmapT :  B*SRC*CH            = 131072   (transposed: [b][src][ch])
//   rel0    :  B*CH*H*W            = 9830400
//   rel1    :  9830400
//   imgA    :  9830400
//   im(tmp) :  9830400
//   rm      :  9830400
//   dep0    :  B*2CH*H*W           = 19660800
//   dep1    :  19660800
//   dm      :  19660800
static const size_t OFF_HMID   = 0;
static const size_t OFF_RELMAP = 131072;
static const size_t OFF_REL0   = 262144;
static const size_t OFF_REL1   = OFF_REL0 + 9830400;
static const size_t OFF_IMGA   = OFF_REL1 + 9830400;
static const size_t OFF_IM     = OFF_IMGA + 9830400;
static const size_t OFF_RM     = OFF_IM   + 9830400;
static const size_t OFF_DEP0   = OFF_RM   + 9830400;
static const size_t OFF_DEP1   = OFF_DEP0 + 19660800;
static const size_t OFF_DM     = OFF_DEP1 + 19660800;
static const size_t SCRATCH_FLOATS = OFF_DM + 19660800;   // 108,396,544 floats

__device__ float g_scratch[SCRATCH_FLOATS];

// ---------------------------------------------------------------------------
// rel_embedding GEMM 1: hmid[b,o,n] = relu(sum_c W1[o,c]*tf[b,c,n] + b1[o])
// grid (128, 4), block 256 (n)
// ---------------------------------------------------------------------------
__global__ void relgemm1(const float* __restrict__ tf,
                         const float* __restrict__ w1,
                         const float* __restrict__ b1,
                         float* __restrict__ hmid)
{
    const int n = threadIdx.x;                 // 0..255
    const int o = blockIdx.x;                  // 0..127
    const int b = blockIdx.y;                  // 0..3
    const float* tfb = tf + (size_t)b * CIN * NN + n;
    const float* wr  = w1 + (size_t)o * CIN;
    float a0 = 0.f, a1 = 0.f, a2 = 0.f, a3 = 0.f;
#pragma unroll 4
    for (int c = 0; c < CIN; c += 4) {
        a0 = fmaf(wr[c + 0], tfb[(size_t)(c + 0) * NN], a0);
        a1 = fmaf(wr[c + 1], tfb[(size_t)(c + 1) * NN], a1);
        a2 = fmaf(wr[c + 2], tfb[(size_t)(c + 2) * NN], a2);
        a3 = fmaf(wr[c + 3], tfb[(size_t)(c + 3) * NN], a3);
    }
    float acc = (a0 + a1) + (a2 + a3) + b1[o];
    hmid[((size_t)b * CHN + o) * NN + n] = fmaxf(acc, 0.f);
}

// ---------------------------------------------------------------------------
// rel_embedding GEMM 2 + transpose:
// relmapT[b,n,o] = sum_c W2[o,c]*hmid[b,c,n] + b2[o]
// grid (256, 4), block 128 (o)
// ---------------------------------------------------------------------------
__global__ void relgemm2(const float* __restrict__ hmid,
                         const float* __restrict__ w2,
                         const float* __restrict__ b2,
                         float* __restrict__ relmapT)
{
    const int o = threadIdx.x;                 // 0..127
    const int n = blockIdx.x;                  // 0..255
    const int b = blockIdx.y;
    const float* wr = w2 + (size_t)o * CHN;
    const float* hb = hmid + (size_t)b * CHN * NN + n;
    float acc = 0.f;
#pragma unroll 8
    for (int c = 0; c < CHN; ++c)
        acc = fmaf(wr[c], hb[(size_t)c * NN], acc);
    relmapT[((size_t)b * SRC + n) * CHN + o] = acc + b2[o];
}

// ---------------------------------------------------------------------------
// Box gather: rel[b,c,y,x] = sum over valid boxes containing (y,x) of
//             relmapT[b, idx(y,box), c]   (nearest-interp row index)
// grid (5, 120, 4) = (x-tile, y, b), block 128 (c)
// ---------------------------------------------------------------------------
__global__ void __launch_bounds__(128)
relgather(const float* __restrict__ relmapT,
          const int* __restrict__ bbox,
          float* __restrict__ rel)
{
    const int c  = threadIdx.x;
    const int x0 = blockIdx.x * 32;
    const int y  = blockIdx.y;
    const int b  = blockIdx.z;

    __shared__ int   sbox[NN * 8];
    __shared__ float sxp[128 * 33];

    for (int i = threadIdx.x; i < NN * 8; i += 128)
        sbox[i] = bbox[(size_t)b * NN * 8 + i];
    __syncthreads();

    float acc[32];
#pragma unroll
    for (int k = 0; k < 32; ++k) acc[k] = 0.f;

    const float* rmb = relmapT + (size_t)b * SRC * CHN;

    for (int j = 0; j < NN; ++j) {
        const int* bx = &sbox[j * 8];
        const int sx1 = bx[0] >> 1, sy1 = bx[1] >> 1, sx2 = bx[2] >> 1, sy2 = bx[3] >> 1;
        const int ox1 = bx[4] >> 1, oy1 = bx[5] >> 1, ox2 = bx[6] >> 1, oy2 = bx[7] >> 1;
        const int sh = sy2 - sy1, sw = sx2 - sx1;
        const int oh = oy2 - oy1, ow = ox2 - ox1;
        if (!((sh >= 5) && (sw >= 5) && (oh >= 5) && (ow >= 5))) continue;

        if (y >= sy1 && y < sy2) {
            int idx = ((y - sy1) * SRC) / max(sh, 1);
            idx = min(idx, SRC - 1);
            float v = rmb[(size_t)idx * CHN + c];
            int xa = max(sx1 - x0, 0);
            int xb = min(sx2 - x0, 32);
            for (int k = xa; k < xb; ++k) acc[k] += v;
        }
        if (y >= oy1 && y < oy2) {
            int idx = ((y - oy1) * SRC) / max(oh, 1);
            idx = min(idx, SRC - 1);
            float v = rmb[(size_t)idx * CHN + c];
            int xa = max(ox1 - x0, 0);
            int xb = min(ox2 - x0, 32);
            for (int k = xa; k < xb; ++k) acc[k] += v;
        }
    }

    // transpose through smem for coalesced global stores
#pragma unroll
    for (int k = 0; k < 32; ++k) sxp[c * 33 + k] = acc[k];
    __syncthreads();
    for (int e = threadIdx.x; e < 128 * 32; e += 128) {
        int cc = e >> 5, xx = e & 31;
        rel[(((size_t)b * CHN + cc) * HH + y) * WW + x0 + xx] = sxp[cc * 33 + xx];
    }
}

// ---------------------------------------------------------------------------
// dep0 = concat(img, rel) along channels
// ---------------------------------------------------------------------------
__global__ void concat_dep(const float* __restrict__ img,
                           const float* __restrict__ rel,
                           float* __restrict__ dep)
{
    const int HW4 = HWSZ / 4;                          // 4800
    int i = blockIdx.x * blockDim.x + threadIdx.x;
    if (i >= BB * 256 * HW4) return;
    int b = i / (256 * HW4);
    int r = i - b * 256 * HW4;
    int c = r / HW4;
    int p = r - c * HW4;
    float4 v = (c < CHN)
        ? reinterpret_cast<const float4*>(img)[((size_t)b * CHN + c) * HW4 + p]
        : reinterpret_cast<const float4*>(rel)[((size_t)b * CHN + (c - CHN)) * HW4 + p];
    reinterpret_cast<float4*>(dep)[i] = v;
}

// ---------------------------------------------------------------------------
// update: d = relu(s + 0.5*m)   (vectorized)
// ---------------------------------------------------------------------------
__global__ void upd_relu(const float4* __restrict__ s,
                         const float4* __restrict__ m,
                         float4* __restrict__ d, int n4)
{
    int i = blockIdx.x * blockDim.x + threadIdx.x;
    if (i >= n4) return;
    float4 a = s[i], mm = m[i], r;
    r.x = fmaxf(fmaf(0.5f, mm.x, a.x), 0.f);
    r.y = fmaxf(fmaf(0.5f, mm.y, a.y), 0.f);
    r.z = fmaxf(fmaf(0.5f, mm.z, a.z), 0.f);
    r.w = fmaxf(fmaf(0.5f, mm.w, a.w), 0.f);
    d[i] = r;
}

// ---------------------------------------------------------------------------
// Direct 3x3 SAME conv, fp32, NCHW.
// Block: 256 threads computes a (64 out-ch) x (8 y) x (32 x) output tile.
// Register tile per thread: 8 out-ch x 8 x-positions (1 row). Input chunk of
// 8 channels staged in SMEM (stride-35 rows -> conflict-free), weights staged
// in SMEM (warp-broadcast reads).
// MODE: 0 = set, 1 = accumulate (+= conv+bias), 2 = set + relu
// Weights: w points at filter-set base, layout [Cout][Cin][3][3].
// ---------------------------------------------------------------------------
template<int MODE>
__global__ void __launch_bounds__(256, 2)
conv3x3(const float* __restrict__ in, const float* __restrict__ w,
        const float* __restrict__ bias, float* __restrict__ out,
        int Cin, int Cout)
{
    __shared__ float in_s[8 * 350];      // 8 ch x 10 rows x (stride 35)
    __shared__ float w_s[64 * 72];       // 64 o x (8 c x 9)

    const int tid = threadIdx.x;
    const int bx  = blockIdx.x;          // 0..74
    const int x0  = (bx % 5) * 32;
    const int y0  = (bx / 5) * 8;
    const int o0  = blockIdx.y * 64;
    const int b   = blockIdx.z;

    const int cg  = tid >> 5;            // warp id = out-channel group (0..7)
    const int pg  = tid & 31;
    const int ty  = pg & 7;              // row within tile
    const int tx8 = (pg >> 3) << 3;      // x base within tile (0,8,16,24)

    float acc[8][8];
#pragma unroll
    for (int i = 0; i < 8; ++i)
#pragma unroll
        for (int j = 0; j < 8; ++j) acc[i][j] = 0.f;

    const int wOS = Cin * 9;
    const float* inb = in + (size_t)b * Cin * HWSZ;

    for (int cc = 0; cc < Cin; cc += 8) {
        __syncthreads();
        // stage input tile (with halo), zero-pad out of bounds
        for (int idx = tid; idx < 8 * 340; idx += 256) {
            int c  = idx / 340;
            int r  = idx - c * 340;
            int iy = r / 34;
            int ix = r - iy * 34;
            int gy = y0 + iy - 1;
            int gx = x0 + ix - 1;
            float v = 0.f;
            if ((unsigned)gy < (unsigned)HH && (unsigned)gx < (unsigned)WW)
                v = inb[(size_t)(cc + c) * HWSZ + gy * WW + gx];
            in_s[c * 350 + iy * 35 + ix] = v;
        }
        // stage weights: 64 o x 8 c x 9 (contiguous per o)
        for (int idx = tid; idx < 64 * 72; idx += 256) {
            int o = idx / 72;
            int r = idx - o * 72;
            w_s[idx] = w[(size_t)(o0 + o) * wOS + cc * 9 + r];
        }
        __syncthreads();

#pragma unroll
        for (int kc = 0; kc < 8; ++kc) {
            const float* wrow = &w_s[(cg * 8) * 72 + kc * 9];
#pragma unroll
            for (int ky = 0; ky < 3; ++ky) {
                float in_r[10];
#pragma unroll
                for (int i = 0; i < 10; ++i)
                    in_r[i] = in_s[kc * 350 + (ty + ky) * 35 + tx8 + i];
#pragma unroll
                for (int kx = 0; kx < 3; ++kx) {
                    float wv[8];
#pragma unroll
                    for (int to = 0; to < 8; ++to)
                        wv[to] = wrow[to * 72 + ky * 3 + kx];
#pragma unroll
                    for (int to = 0; to < 8; ++to)
#pragma unroll
                        for (int px = 0; px < 8; ++px)
                            acc[to][px] = fmaf(wv[to], in_r[px + kx], acc[to][px]);
                }
            }
        }
    }

    // epilogue
#pragma unroll
    for (int to = 0; to < 8; ++to) {
        int o = o0 + cg * 8 + to;
        float bv = bias[o];
        float* op = out + (((size_t)b * Cout + o) * HH + (y0 + ty)) * WW + x0 + tx8;
#pragma unroll
        for (int px = 0; px < 8; ++px) {
            float v = acc[to][px] + bv;
            if (MODE == 1) v += op[px];
            if (MODE == 2) v = fmaxf(v, 0.f);
            op[px] = v;
        }
    }
}

// ---------------------------------------------------------------------------
// Orchestration
// ---------------------------------------------------------------------------
extern "C" void kernel_launch(void* const* d_in, const int* in_sizes, int n_in,
                              void* d_out, int out_size)
{
    const float* ram   = (const float*)d_in[0];   // (B,128,H,W)
    const float* tf    = (const float*)d_in[1];   // (B,1024,256)
    const float* rw1   = (const float*)d_in[2];
    const float* rb1   = (const float*)d_in[3];
    const float* rw2   = (const float*)d_in[4];
    const float* rb2   = (const float*)d_in[5];
    const float* dmcw  = (const float*)d_in[6];   // (4,256,128,3,3)
    const float* dmcb  = (const float*)d_in[7];   // (4,256)
    const float* imw01 = (const float*)d_in[8];   // (2,128,256,3,3)
    const float* imb01 = (const float*)d_in[9];
    const float* imw23 = (const float*)d_in[10];  // (2,128,128,3,3)
    const float* imb23 = (const float*)d_in[11];
    const float* rmw01 = (const float*)d_in[12];
    const float* rmb01 = (const float*)d_in[13];
    const float* rmw23 = (const float*)d_in[14];
    const float* rmb23 = (const float*)d_in[15];
    const float* ew1   = (const float*)d_in[16];  // (128,256,3,3)
    const float* eb1   = (const float*)d_in[17];
    const float* ew2   = (const float*)d_in[18];  // (128,128,3,3)
    const float* eb2   = (const float*)d_in[19];
    const int*   bbox  = (const int*)d_in[20];    // (B,256,8) int32
    float* out = (float*)d_out;

    float* S = nullptr;
    cudaGetSymbolAddress((void**)&S, g_scratch);
    float* hmid    = S + OFF_HMID;
    float* relmapT = S + OFF_RELMAP;
    float* rel0    = S + OFF_REL0;
    float* rel1    = S + OFF_REL1;
    float* imgA    = S + OFF_IMGA;
    float* im      = S + OFF_IM;     // also reused as emb1 tmp
    float* rm      = S + OFF_RM;
    float* dep0    = S + OFF_DEP0;
    float* dep1    = S + OFF_DEP1;
    float* dm      = S + OFF_DM;

    // rel_embedding (two 1x1 convs as GEMMs), rel_map stored transposed
    relgemm1<<<dim3(128, 4), 256>>>(tf, rw1, rb1, hmid);
    relgemm2<<<dim3(256, 4), 128>>>(hmid, rw2, rb2, relmapT);

    // box gather -> rel0
    relgather<<<dim3(5, HH, BB), 128>>>(relmapT, bbox, rel0);

    // dep0 = concat(img, rel0)
    const int nD4 = BB * 256 * HWSZ / 4;   // 4,915,200
    const int nC4 = BB * CHN * HWSZ / 4;   // 2,457,600
    concat_dep<<<(nD4 + 255) / 256, 256>>>(ram, rel0, dep0);

    const size_t DMC_SET = 256 * 128 * 9;  // per-filter-set stride in dmc_w

    // ---- TriGraph iteration 0 (needs dep, img, rel updates) ----
    conv3x3<0><<<dim3(75, 4, BB), 256>>>(ram,  dmcw + 0 * DMC_SET, dmcb + 0 * 256, dm, 128, 256);
    conv3x3<1><<<dim3(75, 4, BB), 256>>>(rel0, dmcw + 2 * DMC_SET, dmcb + 2 * 256, dm, 128, 256);

    conv3x3<0><<<dim3(75, 2, BB), 256>>>(dep0, imw01, imb01, im, 256, 128);
    conv3x3<1><<<dim3(75, 2, BB), 256>>>(rel0, imw23, imb23, im, 128, 128);

    conv3x3<0><<<dim3(75, 2, BB), 256>>>(dep0, rmw01, rmb01, rm, 256, 128);
    conv3x3<1><<<dim3(75, 2, BB), 256>>>(ram,  rmw23, rmb23, rm, 128, 128);

    upd_relu<<<(nD4 + 255) / 256, 256>>>((const float4*)dep0, (const float4*)dm, (float4*)dep1, nD4);
    upd_relu<<<(nC4 + 255) / 256, 256>>>((const float4*)ram,  (const float4*)im, (float4*)imgA, nC4);
    upd_relu<<<(nC4 + 255) / 256, 256>>>((const float4*)rel0, (const float4*)rm, (float4*)rel1, nC4);

    // ---- TriGraph iteration 1 (only dep feeds the output embedding) ----
    conv3x3<0><<<dim3(75, 4, BB), 256>>>(imgA, dmcw + 1 * DMC_SET, dmcb + 1 * 256, dm, 128, 256);
    conv3x3<1><<<dim3(75, 4, BB), 256>>>(rel1, dmcw + 3 * DMC_SET, dmcb + 3 * 256, dm, 128, 256);
    upd_relu<<<(nD4 + 255) / 256, 256>>>((const float4*)dep1, (const float4*)dm, (float4*)dep0, nD4);

    // ---- final embedding: conv -> relu -> conv ----
    conv3x3<2><<<dim3(75, 2, BB), 256>>>(dep0, ew1, eb1, im,  256, 128);  // im reused as tmp
    conv3x3<0><<<dim3(75, 2, BB), 256>>>(im,   ew2, eb2, out, 128, 128);
}

// round 10
// speedup vs baseline: 1.0029x; 1.0029x over previous
#include <cuda_runtime.h>
#include <cuda_bf16.h>

// Problem constants
#define BB   4
#define NN   256
#define CHN  128
#define CIN  1024
#define HH   120
#define WW   160
#define HWSZ (HH * WW)          // 19200
#define SRC  256

// ---------------------------------------------------------------------------
// Scratch (single __device__ global, no allocations anywhere)
// ---------------------------------------------------------------------------
// layout (floats):
//   hmid    :  B*CH*N              = 131072
//   relmapT :  B*SRC*CH            = 131072   (transposed: [b][src][ch])
//   rel0    :  B*CH*H*W            = 9830400
//   rel1    :  9830400
//   imgA    :  9830400
//   im(tmp) :  9830400
//   rm      :  9830400
//   dep0    :  B*2CH*H*W           = 19660800
//   dep1    :  19660800
//   dm      :  19660800
static const size_t OFF_HMID   = 0;
static const size_t OFF_RELMAP = 131072;
static const size_t OFF_REL0   = 262144;
static const size_t OFF_REL1   = OFF_REL0 + 9830400;
static const size_t OFF_IMGA   = OFF_REL1 + 9830400;
static const size_t OFF_IM     = OFF_IMGA + 9830400;
static const size_t OFF_RM     = OFF_IM   + 9830400;
static const size_t OFF_DEP0   = OFF_RM   + 9830400;
static const size_t OFF_DEP1   = OFF_DEP0 + 19660800;
static const size_t OFF_DM     = OFF_DEP1 + 19660800;
static const size_t SCRATCH_FLOATS = OFF_DM + 19660800;   // 108,396,544 floats

__device__ float g_scratch[SCRATCH_FLOATS];

// ---------------------------------------------------------------------------
// rel_embedding GEMM 1: hmid[b,o,n] = relu(sum_c W1[o,c]*tf[b,c,n] + b1[o])
// grid (128, 4), block 256 (n)
// ---------------------------------------------------------------------------
__global__ void relgemm1(const float* __restrict__ tf,
                         const float* __restrict__ w1,
                         const float* __restrict__ b1,
                         float* __restrict__ hmid)
{
    const int n = threadIdx.x;                 // 0..255
    const int o = blockIdx.x;                  // 0..127
    const int b = blockIdx.y;                  // 0..3
    const float* tfb = tf + (size_t)b * CIN * NN + n;
    const float* wr  = w1 + (size_t)o * CIN;
    float a0 = 0.f, a1 = 0.f, a2 = 0.f, a3 = 0.f;
#pragma unroll 4
    for (int c = 0; c < CIN; c += 4) {
        a0 = fmaf(wr[c + 0], tfb[(size_t)(c + 0) * NN], a0);
        a1 = fmaf(wr[c + 1], tfb[(size_t)(c + 1) * NN], a1);
        a2 = fmaf(wr[c + 2], tfb[(size_t)(c + 2) * NN], a2);
        a3 = fmaf(wr[c + 3], tfb[(size_t)(c + 3) * NN], a3);
    }
    float acc = (a0 + a1) + (a2 + a3) + b1[o];
    hmid[((size_t)b * CHN + o) * NN + n] = fmaxf(acc, 0.f);
}

// ---------------------------------------------------------------------------
// rel_embedding GEMM 2 + transpose:
// relmapT[b,n,o] = sum_c W2[o,c]*hmid[b,c,n] + b2[o]
// grid (256, 4), block 128 (o)
// ---------------------------------------------------------------------------
__global__ void relgemm2(const float* __restrict__ hmid,
                         const float* __restrict__ w2,
                         const float* __restrict__ b2,
                         float* __restrict__ relmapT)
{
    const int o = threadIdx.x;                 // 0..127
    const int n = blockIdx.x;                  // 0..255
    const int b = blockIdx.y;
    const float* wr = w2 + (size_t)o * CHN;
    const float* hb = hmid + (size_t)b * CHN * NN + n;
    float acc = 0.f;
#pragma unroll 8
    for (int c = 0; c < CHN; ++c)
        acc = fmaf(wr[c], hb[(size_t)c * NN], acc);
    relmapT[((size_t)b * SRC + n) * CHN + o] = acc + b2[o];
}

// ---------------------------------------------------------------------------
// Box gather: rel[b,c,y,x] = sum over valid boxes containing (y,x) of
//             relmapT[b, idx(y,box), c]   (nearest-interp row index)
// grid (5, 120, 4) = (x-tile, y, b), block 128 (c)
// ---------------------------------------------------------------------------
__global__ void __launch_bounds__(128)
relgather(const float* __restrict__ relmapT,
          const int* __restrict__ bbox,
          float* __restrict__ rel)
{
    const int c  = threadIdx.x;
    const int x0 = blockIdx.x * 32;
    const int y  = blockIdx.y;
    const int b  = blockIdx.z;

    __shared__ int   sbox[NN * 8];
    __shared__ float sxp[128 * 33];

    for (int i = threadIdx.x; i < NN * 8; i += 128)
        sbox[i] = bbox[(size_t)b * NN * 8 + i];
    __syncthreads();

    float acc[32];
#pragma unroll
    for (int k = 0; k < 32; ++k) acc[k] = 0.f;

    const float* rmb = relmapT + (size_t)b * SRC * CHN;

    for (int j = 0; j < NN; ++j) {
        const int* bx = &sbox[j * 8];
        const int sx1 = bx[0] >> 1, sy1 = bx[1] >> 1, sx2 = bx[2] >> 1, sy2 = bx[3] >> 1;
        const int ox1 = bx[4] >> 1, oy1 = bx[5] >> 1, ox2 = bx[6] >> 1, oy2 = bx[7] >> 1;
        const int sh = sy2 - sy1, sw = sx2 - sx1;
        const int oh = oy2 - oy1, ow = ox2 - ox1;
        if (!((sh >= 5) && (sw >= 5) && (oh >= 5) && (ow >= 5))) continue;

        if (y >= sy1 && y < sy2) {
            int idx = ((y - sy1) * SRC) / max(sh, 1);
            idx = min(idx, SRC - 1);
            float v = rmb[(size_t)idx * CHN + c];
            int xa = max(sx1 - x0, 0);
            int xb = min(sx2 - x0, 32);
            for (int k = xa; k < xb; ++k) acc[k] += v;
        }
        if (y >= oy1 && y < oy2) {
            int idx = ((y - oy1) * SRC) / max(oh, 1);
            idx = min(idx, SRC - 1);
            float v = rmb[(size_t)idx * CHN + c];
            int xa = max(ox1 - x0, 0);
            int xb = min(ox2 - x0, 32);
            for (int k = xa; k < xb; ++k) acc[k] += v;
        }
    }

    // transpose through smem for coalesced global stores
#pragma unroll
    for (int k = 0; k < 32; ++k) sxp[c * 33 + k] = acc[k];
    __syncthreads();
    for (int e = threadIdx.x; e < 128 * 32; e += 128) {
        int cc = e >> 5, xx = e & 31;
        rel[(((size_t)b * CHN + cc) * HH + y) * WW + x0 + xx] = sxp[cc * 33 + xx];
    }
}

// ---------------------------------------------------------------------------
// dep0 = concat(img, rel) along channels
// ---------------------------------------------------------------------------
__global__ void concat_dep(const float* __restrict__ img,
                           const float* __restrict__ rel,
                           float* __restrict__ dep)
{
    const int HW4 = HWSZ / 4;                          // 4800
    int i = blockIdx.x * blockDim.x + threadIdx.x;
    if (i >= BB * 256 * HW4) return;
    int b = i / (256 * HW4);
    int r = i - b * 256 * HW4;
    int c = r / HW4;
    int p = r - c * HW4;
    float4 v = (c < CHN)
        ? reinterpret_cast<const float4*>(img)[((size_t)b * CHN + c) * HW4 + p]
        : reinterpret_cast<const float4*>(rel)[((size_t)b * CHN + (c - CHN)) * HW4 + p];
    reinterpret_cast<float4*>(dep)[i] = v;
}

// ---------------------------------------------------------------------------
// update: d = relu(s + 0.5*m)   (vectorized)
// ---------------------------------------------------------------------------
__global__ void upd_relu(const float4* __restrict__ s,
                         const float4* __restrict__ m,
                         float4* __restrict__ d, int n4)
{
    int i = blockIdx.x * blockDim.x + threadIdx.x;
    if (i >= n4) return;
    float4 a = s[i], mm = m[i], r;
    r.x = fmaxf(fmaf(0.5f, mm.x, a.x), 0.f);
    r.y = fmaxf(fmaf(0.5f, mm.y, a.y), 0.f);
    r.z = fmaxf(fmaf(0.5f, mm.z, a.z), 0.f);
    r.w = fmaxf(fmaf(0.5f, mm.w, a.w), 0.f);
    d[i] = r;
}

// ---------------------------------------------------------------------------
// Direct 3x3 SAME conv, fp32, NCHW.
// Block: 256 threads computes a (64 out-ch) x (8 y) x (32 x) output tile.
// Register tile per thread: 8 out-ch x 8 x-positions (1 row). Input chunk of
// 8 channels staged in SMEM (stride-35 rows -> conflict-free), weights staged
// in SMEM (warp-broadcast reads).
// MODE: 0 = set, 1 = accumulate (+= conv+bias), 2 = set + relu
// Weights: w points at filter-set base, layout [Cout][Cin][3][3].
// ---------------------------------------------------------------------------
template<int MODE>
__global__ void __launch_bounds__(256, 2)
conv3x3(const float* __restrict__ in, const float* __restrict__ w,
        const float* __restrict__ bias, float* __restrict__ out,
        int Cin, int Cout)
{
    __shared__ float in_s[8 * 350];      // 8 ch x 10 rows x (stride 35)
    __shared__ float w_s[64 * 72];       // 64 o x (8 c x 9)

    const int tid = threadIdx.x;
    const int bx  = blockIdx.x;          // 0..74
    const int x0  = (bx % 5) * 32;
    const int y0  = (bx / 5) * 8;
    const int o0  = blockIdx.y * 64;
    const int b   = blockIdx.z;

    const int cg  = tid >> 5;            // warp id = out-channel group (0..7)
    const int pg  = tid & 31;
    const int ty  = pg & 7;              // row within tile
    const int tx8 = (pg >> 3) << 3;      // x base within tile (0,8,16,24)

    float acc[8][8];
#pragma unroll
    for (int i = 0; i < 8; ++i)
#pragma unroll
        for (int j = 0; j < 8; ++j) acc[i][j] = 0.f;

    const int wOS = Cin * 9;
    const float* inb = in + (size_t)b * Cin * HWSZ;

    for (int cc = 0; cc < Cin; cc += 8) {
        __syncthreads();
        // stage input tile (with halo), zero-pad out of bounds
        for (int idx = tid; idx < 8 * 340; idx += 256) {
            int c  = idx / 340;
            int r  = idx - c * 340;
            int iy = r / 34;
            int ix = r - iy * 34;
            int gy = y0 + iy - 1;
            int gx = x0 + ix - 1;
            float v = 0.f;
            if ((unsigned)gy < (unsigned)HH && (unsigned)gx < (unsigned)WW)
                v = inb[(size_t)(cc + c) * HWSZ + gy * WW + gx];
            in_s[c * 350 + iy * 35 + ix] = v;
        }
        // stage weights: 64 o x 8 c x 9 (contiguous per o)
        for (int idx = tid; idx < 64 * 72; idx += 256) {
            int o = idx / 72;
            int r = idx - o * 72;
            w_s[idx] = w[(size_t)(o0 + o) * wOS + cc * 9 + r];
        }
        __syncthreads();

#pragma unroll
        for (int kc = 0; kc < 8; ++kc) {
            const float* wrow = &w_s[(cg * 8) * 72 + kc * 9];
#pragma unroll
            for (int ky = 0; ky < 3; ++ky) {
                float in_r[10];
#pragma unroll
                for (int i = 0; i < 10; ++i)
                    in_r[i] = in_s[kc * 350 + (ty + ky) * 35 + tx8 + i];
#pragma unroll
                for (int kx = 0; kx < 3; ++kx) {
                    float wv[8];
#pragma unroll
                    for (int to = 0; to < 8; ++to)
                        wv[to] = wrow[to * 72 + ky * 3 + kx];
#pragma unroll
                    for (int to = 0; to < 8; ++to)
#pragma unroll
                        for (int px = 0; px < 8; ++px)
                            acc[to][px] = fmaf(wv[to], in_r[px + kx], acc[to][px]);
                }
            }
        }
    }

    // epilogue
#pragma unroll
    for (int to = 0; to < 8; ++to) {
        int o = o0 + cg * 8 + to;
        float bv = bias[o];
        float* op = out + (((size_t)b * Cout + o) * HH + (y0 + ty)) * WW + x0 + tx8;
#pragma unroll
        for (int px = 0; px < 8; ++px) {
            float v = acc[to][px] + bv;
            if (MODE == 1) v += op[px];
            if (MODE == 2) v = fmaxf(v, 0.f);
            op[px] = v;
        }
    }
}

// ---------------------------------------------------------------------------
// Orchestration
// ---------------------------------------------------------------------------
extern "C" void kernel_launch(void* const* d_in, const int* in_sizes, int n_in,
                              void* d_out, int out_size)
{
    const float* ram   = (const float*)d_in[0];   // (B,128,H,W)
    const float* tf    = (const float*)d_in[1];   // (B,1024,256)
    const float* rw1   = (const float*)d_in[2];
    const float* rb1   = (const float*)d_in[3];
    const float* rw2   = (const float*)d_in[4];
    const float* rb2   = (const float*)d_in[5];
    const float* dmcw  = (const float*)d_in[6];   // (4,256,128,3,3)
    const float* dmcb  = (const float*)d_in[7];   // (4,256)
    const float* imw01 = (const float*)d_in[8];   // (2,128,256,3,3)
    const float* imb01 = (const float*)d_in[9];
    const float* imw23 = (const float*)d_in[10];  // (2,128,128,3,3)
    const float* imb23 = (const float*)d_in[11];
    const float* rmw01 = (const float*)d_in[12];
    const float* rmb01 = (const float*)d_in[13];
    const float* rmw23 = (const float*)d_in[14];
    const float* rmb23 = (const float*)d_in[15];
    const float* ew1   = (const float*)d_in[16];  // (128,256,3,3)
    const float* eb1   = (const float*)d_in[17];
    const float* ew2   = (const float*)d_in[18];  // (128,128,3,3)
    const float* eb2   = (const float*)d_in[19];
    const int*   bbox  = (const int*)d_in[20];    // (B,256,8) int32
    float* out = (float*)d_out;

    float* S = nullptr;
    cudaGetSymbolAddress((void**)&S, g_scratch);
    float* hmid    = S + OFF_HMID;
    float* relmapT = S + OFF_RELMAP;
    float* rel0    = S + OFF_REL0;
    float* rel1    = S + OFF_REL1;
    float* imgA    = S + OFF_IMGA;
    float* im      = S + OFF_IM;     // also reused as emb1 tmp
    float* rm      = S + OFF_RM;
    float* dep0    = S + OFF_DEP0;
    float* dep1    = S + OFF_DEP1;
    float* dm      = S + OFF_DM;

    // rel_embedding (two 1x1 convs as GEMMs), rel_map stored transposed
    relgemm1<<<dim3(128, 4), 256>>>(tf, rw1, rb1, hmid);
    relgemm2<<<dim3(256, 4), 128>>>(hmid, rw2, rb2, relmapT);

    // box gather -> rel0
    relgather<<<dim3(5, HH, BB), 128>>>(relmapT, bbox, rel0);

    // dep0 = concat(img, rel0)
    const int nD4 = BB * 256 * HWSZ / 4;   // 4,915,200
    const int nC4 = BB * CHN * HWSZ / 4;   // 2,457,600
    concat_dep<<<(nD4 + 255) / 256, 256>>>(ram, rel0, dep0);

    const size_t DMC_SET = 256 * 128 * 9;  // per-filter-set stride in dmc_w

    // ---- TriGraph iteration 0 (needs dep, img, rel updates) ----
    conv3x3<0><<<dim3(75, 4, BB), 256>>>(ram,  dmcw + 0 * DMC_SET, dmcb + 0 * 256, dm, 128, 256);
    conv3x3<1><<<dim3(75, 4, BB), 256>>>(rel0, dmcw + 2 * DMC_SET, dmcb + 2 * 256, dm, 128, 256);

    conv3x3<0><<<dim3(75, 2, BB), 256>>>(dep0, imw01, imb01, im, 256, 128);
    conv3x3<1><<<dim3(75, 2, BB), 256>>>(rel0, imw23, imb23, im, 128, 128);

    conv3x3<0><<<dim3(75, 2, BB), 256>>>(dep0, rmw01, rmb01, rm, 256, 128);
    conv3x3<1><<<dim3(75, 2, BB), 256>>>(ram,  rmw23, rmb23, rm, 128, 128);

    upd_relu<<<(nD4 + 255) / 256, 256>>>((const float4*)dep0, (const float4*)dm, (float4*)dep1, nD4);
    upd_relu<<<(nC4 + 255) / 256, 256>>>((const float4*)ram,  (const float4*)im, (float4*)imgA, nC4);
    upd_relu<<<(nC4 + 255) / 256, 256>>>((const float4*)rel0, (const float4*)rm, (float4*)rel1, nC4);

    // ---- TriGraph iteration 1 (only dep feeds the output embedding) ----
    conv3x3<0><<<dim3(75, 4, BB), 256>>>(imgA, dmcw + 1 * DMC_SET, dmcb + 1 * 256, dm, 128, 256);
    conv3x3<1><<<dim3(75, 4, BB), 256>>>(rel1, dmcw + 3 * DMC_SET, dmcb + 3 * 256, dm, 128, 256);
    upd_relu<<<(nD4 + 255) / 256, 256>>>((const float4*)dep1, (const float4*)dm, (float4*)dep0, nD4);

    // ---- final embedding: conv -> relu -> conv ----
    conv3x3<2><<<dim3(75, 2, BB), 256>>>(dep0, ew1, eb1, im,  256, 128);  // im reused as tmp
    conv3x3<0><<<dim3(75, 2, BB), 256>>>(im,   ew2, eb2, out, 128, 128);
}